// round 10
// baseline (speedup 1.0000x reference)
#include <cuda_runtime.h>
#include <cuda_bf16.h>
#include <cstdint>

// GCN: 3 layers, N=50000 nodes, D=64 features, E=800000 edges (+ self loops).
// out_l = dis * (scatter_add(g) + g) + b,  g = (X @ W) * dis,  dis = rsqrt(deg+1)

#define N_NODES 50000
#define N_EDGES 800000
#define D 64
#define ROWS_PER_BLK 16

// Scratch (allocation-free rule: __device__ globals)
__device__ float g_buf[N_NODES * D];    // (X@W) * dis[row]
__device__ float acc_buf[N_NODES * D];  // edge-aggregated sums
__device__ float x_buf[N_NODES * D];    // layer activations
__device__ int   src32[N_EDGES];
__device__ int   dst32[N_EDGES];
__device__ int   deg_buf[N_NODES];
__device__ float dis_buf[N_NODES];
__device__ int   ei_is64;               // 1 if edge_index stored as int64

// Detect edge_index dtype: for int64 values in [0, 50000), every odd 32-bit
// word is 0. For int32, odd words are random node ids (~never all zero).
__global__ void detect_kernel(const int* __restrict__ raw) {
    __shared__ int any_nonzero;
    if (threadIdx.x == 0) any_nonzero = 0;
    __syncthreads();
    // check odd words 1,3,...,4095 (2048 samples)
    for (int i = threadIdx.x; i < 2048; i += blockDim.x) {
        if (raw[2 * i + 1] != 0) any_nonzero = 1;
    }
    __syncthreads();
    if (threadIdx.x == 0) ei_is64 = (any_nonzero == 0) ? 1 : 0;
}

// Normalize edges to int32 src/dst regardless of stored dtype.
__global__ void convert_kernel(const void* __restrict__ raw) {
    int e = blockIdx.x * blockDim.x + threadIdx.x;
    if (e >= N_EDGES) return;
    if (ei_is64) {
        const long long* p = (const long long*)raw;
        src32[e] = (int)p[e];
        dst32[e] = (int)p[N_EDGES + e];
    } else {
        const int* p = (const int*)raw;
        src32[e] = p[e];
        dst32[e] = p[N_EDGES + e];
    }
}

__global__ void zero_deg_kernel() {
    int i = blockIdx.x * blockDim.x + threadIdx.x;
    if (i < N_NODES) deg_buf[i] = 0;
}

__global__ void count_deg_kernel() {
    int e = blockIdx.x * blockDim.x + threadIdx.x;
    if (e < N_EDGES) atomicAdd(&deg_buf[dst32[e]], 1);
}

__global__ void compute_dis_kernel() {
    int i = blockIdx.x * blockDim.x + threadIdx.x;
    if (i < N_NODES) {
        // +1 for the self loop; always > 0 so no zero guard needed
        dis_buf[i] = rsqrtf((float)(deg_buf[i] + 1));
    }
}

// h = X @ W (64x64), then g = h * dis[row]; also zeroes acc for this layer.
// Block: 256 threads, handles 16 rows. W staged in smem.
// X == nullptr means "read activations from x_buf".
__global__ __launch_bounds__(256) void gemm_scale_kernel(
    const float* __restrict__ X, const float* __restrict__ W) {
    __shared__ float Ws[D * D];
    __shared__ float Xs[ROWS_PER_BLK * D];

    const float* Xp = (X == nullptr) ? x_buf : X;

    int tid = threadIdx.x;
    int rowBase = blockIdx.x * ROWS_PER_BLK;

    for (int i = tid; i < D * D; i += 256) Ws[i] = W[i];
    for (int i = tid; i < ROWS_PER_BLK * D; i += 256) Xs[i] = Xp[rowBase * D + i];
    __syncthreads();

    int c  = tid & 63;       // output column
    int rs = tid >> 6;       // 0..3

    #pragma unroll
    for (int rr = 0; rr < ROWS_PER_BLK / 4; rr++) {
        int rl = rr * 4 + rs;
        float sum = 0.f;
        #pragma unroll
        for (int k = 0; k < D; k++)
            sum = fmaf(Xs[rl * D + k], Ws[k * D + c], sum);
        int row = rowBase + rl;
        int idx = row * D + c;
        g_buf[idx]   = sum * dis_buf[row];
        acc_buf[idx] = 0.f;
    }
}

// One edge per warp (32 lanes); lane t handles columns t and t+32.
// The two atomicAdds per thread are 128B apart -> ptxas cannot fuse them into
// the vectorized red.global form (which traps on this address space).
__global__ __launch_bounds__(256) void scatter_kernel() {
    long long gid = (long long)blockIdx.x * blockDim.x + threadIdx.x;
    int e = (int)(gid >> 5);
    if (e >= N_EDGES) return;
    int t = (int)(gid & 31);

    int s = src32[e];
    int d = dst32[e];

    float v0 = g_buf[s * D + t];
    float v1 = g_buf[s * D + t + 32];
    atomicAdd(&acc_buf[d * D + t], v0);
    atomicAdd(&acc_buf[d * D + t + 32], v1);
}

// out = dis[row] * (acc + g) + b[c]  (self loop = +g), optional relu.
// use_out == 0 -> write to x_buf (next layer's activations).
__global__ __launch_bounds__(256) void finalize_kernel(
    const float* __restrict__ b, float* __restrict__ out,
    int do_relu, int use_out) {
    int i = blockIdx.x * blockDim.x + threadIdx.x;
    if (i >= N_NODES * D) return;
    int row = i >> 6;
    int c   = i & 63;
    float v = dis_buf[row] * (acc_buf[i] + g_buf[i]) + b[c];
    if (do_relu) v = fmaxf(v, 0.f);
    if (use_out) out[i] = v;
    else         x_buf[i] = v;
}

extern "C" void kernel_launch(void* const* d_in, const int* in_sizes, int n_in,
                              void* d_out, int out_size) {
    const float* x  = (const float*)d_in[0];
    const void*  ei = d_in[1];
    const float* W0 = (const float*)d_in[2];
    const float* b0 = (const float*)d_in[3];
    const float* W1 = (const float*)d_in[4];
    const float* b1 = (const float*)d_in[5];
    const float* W2 = (const float*)d_in[6];
    const float* b2 = (const float*)d_in[7];
    float* out = (float*)d_out;

    // edge normalization + degree + dis
    detect_kernel<<<1, 256>>>((const int*)ei);
    convert_kernel<<<(N_EDGES + 255) / 256, 256>>>(ei);
    zero_deg_kernel<<<(N_NODES + 255) / 256, 256>>>();
    count_deg_kernel<<<(N_EDGES + 255) / 256, 256>>>();
    compute_dis_kernel<<<(N_NODES + 255) / 256, 256>>>();

    const int gemm_blocks    = N_NODES / ROWS_PER_BLK;                       // 3125
    const int scatter_blocks = (int)(((long long)N_EDGES * 32 + 255) / 256); // 100000
    const int elem_blocks    = (N_NODES * D + 255) / 256;

    // Layer 0: x -> x_buf (relu)
    gemm_scale_kernel<<<gemm_blocks, 256>>>(x, W0);
    scatter_kernel<<<scatter_blocks, 256>>>();
    finalize_kernel<<<elem_blocks, 256>>>(b0, out, 1, 0);

    // Layer 1: x_buf -> x_buf (relu)
    gemm_scale_kernel<<<gemm_blocks, 256>>>(nullptr, W1);
    scatter_kernel<<<scatter_blocks, 256>>>();
    finalize_kernel<<<elem_blocks, 256>>>(b1, out, 1, 0);

    // Layer 2: x_buf -> out (no relu)
    gemm_scale_kernel<<<gemm_blocks, 256>>>(nullptr, W2);
    scatter_kernel<<<scatter_blocks, 256>>>();
    finalize_kernel<<<elem_blocks, 256>>>(b2, out, 0, 1);
}

// round 15
// speedup vs baseline: 1.1313x; 1.1313x over previous
#include <cuda_runtime.h>
#include <cuda_bf16.h>
#include <cstdint>

// GCN: 3 layers, N=50000 nodes, D=64, E=800000 edges (+ self loops).
// out_l = dis * (sum_in g[src] + g[v]) + b,  g = (X @ W) * dis,  dis = rsqrt(deg+1)
// CSR-by-dst built per call; aggregation = warp-per-node register gather (no atomics).

#define N_NODES 50000
#define N_EDGES 800000
#define D 64
#define ROWS_PER_BLK 16
#define SCAN_T 1024
#define CHUNK ((N_NODES + SCAN_T - 1) / SCAN_T)   // 49

// Scratch (allocation-free rule: __device__ globals)
__device__ float g_buf[N_NODES * D];     // (X@W) * dis[row]
__device__ float x_buf[N_NODES * D];     // layer activations
__device__ int   adj_src[N_EDGES];       // CSR adjacency (src ids grouped by dst)
__device__ int   row_ptr[N_NODES + 1];
__device__ int   cursor[N_NODES];
__device__ int   deg_buf[N_NODES];
__device__ float dis_buf[N_NODES];
__device__ int   ei_is64;                // 1 if edge_index stored as int64

// Detect edge_index dtype: int64 values < 50000 -> every odd 32-bit word is 0.
__global__ void detect_kernel(const int* __restrict__ raw) {
    __shared__ int any_nonzero;
    if (threadIdx.x == 0) any_nonzero = 0;
    __syncthreads();
    for (int i = threadIdx.x; i < 2048; i += blockDim.x)
        if (raw[2 * i + 1] != 0) any_nonzero = 1;
    __syncthreads();
    if (threadIdx.x == 0) ei_is64 = (any_nonzero == 0) ? 1 : 0;
}

__global__ void zero_deg_kernel() {
    int i = blockIdx.x * blockDim.x + threadIdx.x;
    if (i < N_NODES) deg_buf[i] = 0;
}

__global__ void count_deg_kernel(const void* __restrict__ raw) {
    int e = blockIdx.x * blockDim.x + threadIdx.x;
    if (e >= N_EDGES) return;
    int d = ei_is64 ? (int)((const long long*)raw)[N_EDGES + e]
                    : ((const int*)raw)[N_EDGES + e];
    atomicAdd(&deg_buf[d], 1);
}

// One block: exclusive scan of deg -> row_ptr (+cursor copy), dis = rsqrt(deg+1).
__global__ __launch_bounds__(SCAN_T) void scan_kernel() {
    __shared__ int partial[SCAN_T];
    int t = threadIdx.x;
    int start = t * CHUNK;
    int end = min(start + CHUNK, N_NODES);
    int s = 0;
    for (int i = start; i < end; i++) s += deg_buf[i];
    partial[t] = s;
    __syncthreads();
    for (int off = 1; off < SCAN_T; off <<= 1) {
        int v = (t >= off) ? partial[t - off] : 0;
        __syncthreads();
        partial[t] += v;
        __syncthreads();
    }
    int run = partial[t] - s;   // exclusive prefix
    for (int i = start; i < end; i++) {
        row_ptr[i] = run;
        cursor[i]  = run;
        dis_buf[i] = rsqrtf((float)(deg_buf[i] + 1));
        run += deg_buf[i];
    }
    if (t == SCAN_T - 1) row_ptr[N_NODES] = partial[SCAN_T - 1];
}

__global__ void fill_adj_kernel(const void* __restrict__ raw) {
    int e = blockIdx.x * blockDim.x + threadIdx.x;
    if (e >= N_EDGES) return;
    int s, d;
    if (ei_is64) {
        const long long* p = (const long long*)raw;
        s = (int)p[e]; d = (int)p[N_EDGES + e];
    } else {
        const int* p = (const int*)raw;
        s = p[e]; d = p[N_EDGES + e];
    }
    int pos = atomicAdd(&cursor[d], 1);
    adj_src[pos] = s;
}

// g = (X @ W) * dis[row]. 256 threads / 16 rows per block.
// Thread t: row rl = t>>4, cols cg..cg+3 (cg = (t&15)*4) -> float4 smem reads.
__global__ __launch_bounds__(256) void gemm_scale_kernel(
    const float* __restrict__ X, const float* __restrict__ W) {
    __shared__ float Ws[D * D];
    __shared__ float Xs[ROWS_PER_BLK * D];

    const float* Xp = (X == nullptr) ? x_buf : X;
    int tid = threadIdx.x;
    int rowBase = blockIdx.x * ROWS_PER_BLK;

    #pragma unroll
    for (int i = tid; i < D * D; i += 256) Ws[i] = W[i];
    #pragma unroll
    for (int i = tid; i < ROWS_PER_BLK * D; i += 256) Xs[i] = Xp[rowBase * D + i];
    __syncthreads();

    int rl = tid >> 4;          // local row 0..15
    int cg = (tid & 15) * 4;    // col group

    const float4* Ws4 = reinterpret_cast<const float4*>(Ws);
    float4 sum = make_float4(0.f, 0.f, 0.f, 0.f);
    #pragma unroll
    for (int k = 0; k < D; k++) {
        float xv = Xs[rl * D + k];
        float4 w = Ws4[k * (D / 4) + (cg >> 2)];
        sum.x = fmaf(xv, w.x, sum.x);
        sum.y = fmaf(xv, w.y, sum.y);
        sum.z = fmaf(xv, w.z, sum.z);
        sum.w = fmaf(xv, w.w, sum.w);
    }
    int row = rowBase + rl;
    float dv = dis_buf[row];
    sum.x *= dv; sum.y *= dv; sum.z *= dv; sum.w *= dv;
    *reinterpret_cast<float4*>(&g_buf[row * D + cg]) = sum;
}

// Warp per dst node: register-accumulate incoming g rows + self loop,
// fused epilogue: out = dis*acc + b (opt relu). Lane t owns cols 2t, 2t+1.
__global__ __launch_bounds__(256) void gather_kernel(
    const float* __restrict__ b, float* __restrict__ out,
    int do_relu, int use_out) {
    int warp = (blockIdx.x * 256 + threadIdx.x) >> 5;
    if (warp >= N_NODES) return;
    int t = threadIdx.x & 31;
    int v = warp;

    // self loop
    float2 acc = *reinterpret_cast<const float2*>(&g_buf[v * D + 2 * t]);

    int beg = row_ptr[v], end = row_ptr[v + 1];
    int s_next = (beg < end) ? adj_src[beg] : 0;
    for (int e = beg; e < end; e++) {
        int s = s_next;
        if (e + 1 < end) s_next = adj_src[e + 1];
        float2 gv = *reinterpret_cast<const float2*>(&g_buf[s * D + 2 * t]);
        acc.x += gv.x;
        acc.y += gv.y;
    }

    float dv = dis_buf[v];
    float2 bb = *reinterpret_cast<const float2*>(&b[2 * t]);
    float o0 = fmaf(dv, acc.x, bb.x);
    float o1 = fmaf(dv, acc.y, bb.y);
    if (do_relu) { o0 = fmaxf(o0, 0.f); o1 = fmaxf(o1, 0.f); }
    float* dst = use_out ? out : x_buf;
    *reinterpret_cast<float2*>(&dst[v * D + 2 * t]) = make_float2(o0, o1);
}

extern "C" void kernel_launch(void* const* d_in, const int* in_sizes, int n_in,
                              void* d_out, int out_size) {
    const float* x  = (const float*)d_in[0];
    const void*  ei = d_in[1];
    const float* W0 = (const float*)d_in[2];
    const float* b0 = (const float*)d_in[3];
    const float* W1 = (const float*)d_in[4];
    const float* b1 = (const float*)d_in[5];
    const float* W2 = (const float*)d_in[6];
    const float* b2 = (const float*)d_in[7];
    float* out = (float*)d_out;

    const int edge_blocks = (N_EDGES + 255) / 256;
    const int node_blocks = (N_NODES + 255) / 256;

    // CSR build + dis
    detect_kernel<<<1, 256>>>((const int*)ei);
    zero_deg_kernel<<<node_blocks, 256>>>();
    count_deg_kernel<<<edge_blocks, 256>>>(ei);
    scan_kernel<<<1, SCAN_T>>>();
    fill_adj_kernel<<<edge_blocks, 256>>>(ei);

    const int gemm_blocks   = N_NODES / ROWS_PER_BLK;              // 3125
    const int gather_blocks = (N_NODES * 32 + 255) / 256;          // 6250

    // Layer 0: x -> x_buf (relu)
    gemm_scale_kernel<<<gemm_blocks, 256>>>(x, W0);
    gather_kernel<<<gather_blocks, 256>>>(b0, out, 1, 0);

    // Layer 1: x_buf -> x_buf (relu)
    gemm_scale_kernel<<<gemm_blocks, 256>>>(nullptr, W1);
    gather_kernel<<<gather_blocks, 256>>>(b1, out, 1, 0);

    // Layer 2: x_buf -> out (no relu)
    gemm_scale_kernel<<<gemm_blocks, 256>>>(nullptr, W2);
    gather_kernel<<<gather_blocks, 256>>>(b2, out, 0, 1);
}